// round 8
// baseline (speedup 1.0000x reference)
#include <cuda_runtime.h>
#include <math.h>

// Fixed shapes: x (4, 32, 8192, 64) fp32, token_positions = arange(8192)
#define SEQ       8192
#define NF4_ROW   16                  // 64 floats / 4 per row
#define BH        128                 // 4*32 slices
#define CHUNK     4                   // bh-slices per thread
#define NCHUNK    (BH / CHUNK)        // 32
#define PTILE     16                  // positions per block
#define SLICE_F4  (SEQ * NF4_ROW)     // 131072 float4 per slice
#define LOG2_THETA 13.2877123795494489f // log2(10000), fp32

// R7 structure exactly; single change: plain LDG/STG instead of __ldcs/__stcs
// (A/B test — R2's 83.2%-DRAM kernel used plain ops; all 78.8-79.8% fused
// variants used .cs).
__global__ void __launch_bounds__(256, 6)
rope_fused(const float4* __restrict__ x, float4* __restrict__ out,
           const int* __restrict__ pos) {
    __shared__ float2 s_tab[PTILE][32];   // 4 KB block trig table

    int t     = threadIdx.x;
    int j     = t & (NF4_ROW - 1);               // float4 within row (0..15)
    int pl    = t >> 4;                          // local position (0..15)
    int b     = blockIdx.x;
    int p0    = (b & (SEQ / PTILE - 1)) * PTILE; // position tile base
    int chunk = b >> 9;                          // 0..31 (which 4 bh-slices)

    // ---- Issue ALL global loads FIRST: DRAM latency covers the trig phase ----
    size_t base = (size_t)chunk * CHUNK * SLICE_F4
                + (size_t)(p0 + pl) * NF4_ROW + j;
    const float4* xp = x   + base;
    float4*       op = out + base;

    float4 v0 = xp[0 * SLICE_F4];
    float4 v1 = xp[1 * SLICE_F4];
    float4 v2 = xp[2 * SLICE_F4];
    float4 v3 = xp[3 * SLICE_F4];

    // ---- Trig phase (runs under the memory latency of the loads above) ----
    // invf = 10000^(-k/32) fp32 exp2f: rel_err 6.3e-5 measured (budget 1e-3).
    {
        int k  = t & 31;                 // frequency
        int lp = t >> 5;                 // local positions lp, lp+8
        float invf = exp2f(-(float)k * (LOG2_THETA / 32.0f));
        float s, c;
        float pa = (float)__ldg(&pos[p0 + lp]) * invf;
        sincosf(pa, &s, &c);
        s_tab[lp][k] = make_float2(c, s);
        float pb = (float)__ldg(&pos[p0 + lp + 8]) * invf;
        sincosf(pb, &s, &c);
        s_tab[lp + 8][k] = make_float2(c, s);
    }
    __syncthreads();

    float4 tr = *(const float4*)&s_tab[pl][2 * j];   // {c0, s0, c1, s1}

    // ---- Rotate + store ----
    float4 o;
    o.x = tr.x * v0.x - tr.y * v0.y;  o.y = tr.y * v0.x + tr.x * v0.y;
    o.z = tr.z * v0.z - tr.w * v0.w;  o.w = tr.w * v0.z + tr.z * v0.w;
    op[0 * SLICE_F4] = o;
    o.x = tr.x * v1.x - tr.y * v1.y;  o.y = tr.y * v1.x + tr.x * v1.y;
    o.z = tr.z * v1.z - tr.w * v1.w;  o.w = tr.w * v1.z + tr.z * v1.w;
    op[1 * SLICE_F4] = o;
    o.x = tr.x * v2.x - tr.y * v2.y;  o.y = tr.y * v2.x + tr.x * v2.y;
    o.z = tr.z * v2.z - tr.w * v2.w;  o.w = tr.w * v2.z + tr.z * v2.w;
    op[2 * SLICE_F4] = o;
    o.x = tr.x * v3.x - tr.y * v3.y;  o.y = tr.y * v3.x + tr.x * v3.y;
    o.z = tr.z * v3.z - tr.w * v3.w;  o.w = tr.w * v3.z + tr.z * v3.w;
    op[3 * SLICE_F4] = o;
}

extern "C" void kernel_launch(void* const* d_in, const int* in_sizes, int n_in,
                              void* d_out, int out_size) {
    const float4* x   = (const float4*)d_in[0];
    const int*    pos = (const int*)d_in[1];
    float4*       out = (float4*)d_out;

    // grid: 512 position-tiles * 32 bh-chunks = 16384 blocks of 256
    int nblocks = (SEQ / PTILE) * NCHUNK;
    rope_fused<<<nblocks, 256>>>(x, out, pos);
}

// round 9
// speedup vs baseline: 1.0183x; 1.0183x over previous
#include <cuda_runtime.h>
#include <math.h>

// Fixed shapes: x (4, 32, 8192, 64) fp32, token_positions = arange(8192)
#define SEQ       8192
#define NF4_ROW   16                    // 64 floats / 4 per row
#define SLICE_F4  (SEQ * NF4_ROW)       // 131072 float4 per (b,h) slice
#define N4_TOTAL  (128 * SLICE_F4)      // 16,777,216 float4 total
#define HALF_F4   (N4_TOTAL / 2)        // = 64 * SLICE_F4 -> same (p,j)!
#define LOG2_THETA 13.2877123795494489f // log2(10000), fp32

// R2-main's exact winning address pattern (i, i + N/2: two linear streams,
// DRAM hit 83.2% there), with the trig computed inline per thread instead of
// read from a table. i + HALF_F4 is an exact multiple of SLICE_F4 past i, so
// both elements share the same (position, freq) -> one set of cos/sin.
// No smem, no barrier, no block prologue.
__global__ void __launch_bounds__(256, 6)
rope_inline(const float4* __restrict__ x, float4* __restrict__ out,
            const int* __restrict__ pos) {
    int i = blockIdx.x * 256 + threadIdx.x;      // 0 .. HALF_F4-1
    int j = i & (NF4_ROW - 1);                   // float4 within row
    int p = (i >> 4) & (SEQ - 1);                // seq position

    // ---- Front-batch both loads: DRAM latency covers the trig below ----
    float4 v0 = x[i];
    float4 v1 = x[i + HALF_F4];

    // ---- Inline trig for pairs k = 2j, 2j+1 ----
    // invf via fp32 exp2f: measured rel_err 6.3e-5 (budget 1e-3).
    float posf = (float)__ldg(&pos[p]);
    float invf0 = exp2f(-(float)(2 * j)     * (LOG2_THETA / 32.0f));
    float invf1 = exp2f(-(float)(2 * j + 1) * (LOG2_THETA / 32.0f));
    float c0, s0, c1, s1;
    sincosf(posf * invf0, &s0, &c0);
    sincosf(posf * invf1, &s1, &c1);

    // ---- Rotate + store ----
    float4 o;
    o.x = c0 * v0.x - s0 * v0.y;  o.y = s0 * v0.x + c0 * v0.y;
    o.z = c1 * v0.z - s1 * v0.w;  o.w = s1 * v0.z + c1 * v0.w;
    out[i] = o;
    o.x = c0 * v1.x - s0 * v1.y;  o.y = s0 * v1.x + c0 * v1.y;
    o.z = c1 * v1.z - s1 * v1.w;  o.w = s1 * v1.z + c1 * v1.w;
    out[i + HALF_F4] = o;
}

extern "C" void kernel_launch(void* const* d_in, const int* in_sizes, int n_in,
                              void* d_out, int out_size) {
    const float4* x   = (const float4*)d_in[0];
    const int*    pos = (const int*)d_in[1];
    float4*       out = (float4*)d_out;

    // 8,388,608 threads = 32768 blocks of 256 (same grid shape as R2-main)
    rope_inline<<<HALF_F4 / 256, 256>>>(x, out, pos);
}